// round 14
// baseline (speedup 1.0000x reference)
#include <cuda_runtime.h>
#include <cuda_fp16.h>
#include <cstdint>

#define BB 8
#define SS 2048
#define FF 1024
#define NEGV -1000000000.0f

// Persistent hi/lo split operands, fp16 (allocation-free rule: __device__ globals)
__device__ __half g_Xh [BB * SS * FF];
__device__ __half g_Xl [BB * SS * FF];
__device__ __half g_Wh [3 * FF * FF];
__device__ __half g_Wl [3 * FF * FF];
__device__ __half g_Qh [BB * SS * FF];   // Q-lo never consumed (2-term scores) -> not stored
__device__ __half g_Kh [BB * SS * FF];
__device__ __half g_Kl [BB * SS * FF];
__device__ __half g_Vth[BB * FF * SS];   // V transposed [b][f][s]
__device__ __half g_Vtl[BB * FF * SS];
__device__ float  g_S  [BB * SS * SS];   // raw masked scores (fp32)
__device__ __half g_Ph [BB * SS * SS];   // probs hi (P-lo dropped: 2-term AV)

// Dynamic smem.
// 3-term (qkv): stage = [Ah 8K][Al 8K][Bh 8K][Bl 8K] = 32K; 3 stages = 96K.
// 2-term (scores/av): stage = [Ah 8K][Bh 8K][Bl 8K] = 24K; 3 stages = 72K.
// qkv V-transpose epilogue reuses [0, 128*132*4)=67584 after pipeline drains.
extern __shared__ __align__(1024) char dsm[];
#define BUF_STRIDE 32768u
#define OFF_AL  8192u
#define OFF_BH 16384u
#define OFF_BL 24576u
#define SMEM_BYTES  98304   // 3 * 32K (qkv)

#define BUF2_STRIDE 24576u
#define OFF2_BH  8192u
#define OFF2_BL 16384u
#define SMEM_BYTES2 73728   // 3 * 24K (scores/av)

#define SW128(o) ((o) ^ (((o) >> 3) & 0x70))
// Packed tile: two 64B tile-rows (32 fp16 each) per 128B smem row, SW128 swizzled.
// row in [0,128), s = 16B segment (8 fp16) in [0,4)
#define SWP(row, s) SW128((((row) >> 1) * 128) + (((((row) & 1) * 4) + (s)) * 16))

static __device__ __forceinline__ uint32_t smem_u32(const void* p) {
    uint32_t a;
    asm("{ .reg .u64 t; cvta.to.shared.u64 t, %1; cvt.u32.u64 %0, t; }" : "=r"(a) : "l"(p));
    return a;
}
// Paired split: writes half2 at even element index
static __device__ __forceinline__ void split_store_h2(
    __half* __restrict__ hi, __half* __restrict__ lo, size_t idx, float v0, float v1)
{
    __half h0 = __float2half_rn(v0);
    __half h1 = __float2half_rn(v1);
    __half l0 = __float2half_rn(v0 - __half2float(h0));
    __half l1 = __float2half_rn(v1 - __half2float(h1));
    *(__half2*)&hi[idx] = __halves2half2(h0, h1);
    *(__half2*)&lo[idx] = __halves2half2(l0, l1);
}

// NOTE: non-volatile — pure register math; lets ptxas interleave with LDSM.
static __device__ __forceinline__ void mma_f16(float* c, const uint32_t* a,
                                               uint32_t b0, uint32_t b1)
{
    asm("mma.sync.aligned.m16n8k16.row.col.f32.f16.f16.f32 "
        "{%0,%1,%2,%3}, {%4,%5,%6,%7}, {%8,%9}, {%0,%1,%2,%3};"
        : "+f"(c[0]), "+f"(c[1]), "+f"(c[2]), "+f"(c[3])
        : "r"(a[0]), "r"(a[1]), "r"(a[2]), "r"(a[3]), "r"(b0), "r"(b1));
}

#define LDSM4(dst, addr) \
    asm volatile("ldmatrix.sync.aligned.m8n8.x4.shared.b16 {%0,%1,%2,%3}, [%4];" \
        : "=r"((dst)[0]), "=r"((dst)[1]), "=r"((dst)[2]), "=r"((dst)[3]) : "r"(addr))

// ---------------------------------------------------------------------------
// 3-term GEMM core (qkv): C = Ah*Bh + Ah*Bl + Al*Bh. 128x128 tile, K=32 chunks.
// ---------------------------------------------------------------------------

static __device__ __forceinline__ void stage4(
    const __half* gAh, const __half* gAl, int ldA,
    const __half* gBh, const __half* gBl, int ldB, uint32_t sbuf)
{
    const int t = threadIdx.x;
    #pragma unroll
    for (int i = 0; i < 2; ++i) {
        int v   = t + i * 256;          // 512 16B segments per tile
        int row = v >> 2;
        int s   = v & 3;
        uint32_t off = SWP(row, s);
        const __half* pah = gAh + (size_t)row * ldA + s * 8;
        const __half* pal = gAl + (size_t)row * ldA + s * 8;
        const __half* pbh = gBh + (size_t)row * ldB + s * 8;
        const __half* pbl = gBl + (size_t)row * ldB + s * 8;
        asm volatile("cp.async.cg.shared.global [%0], [%1], 16;" :: "r"(sbuf + off),          "l"(pah) : "memory");
        asm volatile("cp.async.cg.shared.global [%0], [%1], 16;" :: "r"(sbuf + OFF_AL + off), "l"(pal) : "memory");
        asm volatile("cp.async.cg.shared.global [%0], [%1], 16;" :: "r"(sbuf + OFF_BH + off), "l"(pbh) : "memory");
        asm volatile("cp.async.cg.shared.global [%0], [%1], 16;" :: "r"(sbuf + OFF_BL + off), "l"(pbl) : "memory");
    }
}

static __device__ __forceinline__ void compute_chunk3(uint32_t sbuf, float acc[2][8][4])
{
    const int lane = threadIdx.x & 31;
    const int w    = threadIdx.x >> 5;
    const int wm   = w & 3;
    const int wn   = w >> 2;
    const int r    = lane & 7;
    const int mid  = lane >> 3;

    #pragma unroll
    for (int ki = 0; ki < 2; ++ki) {
        uint32_t aH[2][4], aL[2][4];
        #pragma unroll
        for (int mi = 0; mi < 2; ++mi) {
            int row = wm * 32 + mi * 16 + (mid & 1) * 8 + r;
            int s   = ki * 2 + (mid >> 1);
            uint32_t off = SWP(row, s);
            LDSM4(aH[mi], sbuf + off);
            LDSM4(aL[mi], sbuf + OFF_AL + off);
        }
        #pragma unroll
        for (int pj = 0; pj < 4; ++pj) {
            uint32_t bH[4], bL[4];
            int row = wn * 64 + (pj * 2 + (mid >> 1)) * 8 + r;
            int s   = ki * 2 + (mid & 1);
            uint32_t off = SWP(row, s);
            LDSM4(bH, sbuf + OFF_BH + off);
            LDSM4(bL, sbuf + OFF_BL + off);
            #pragma unroll
            for (int mi = 0; mi < 2; ++mi) {
                float* c0 = acc[mi][pj * 2 + 0];
                float* c1 = acc[mi][pj * 2 + 1];
                mma_f16(c0, aH[mi], bH[0], bH[1]);
                mma_f16(c0, aH[mi], bL[0], bL[1]);
                mma_f16(c0, aL[mi], bH[0], bH[1]);
                mma_f16(c1, aH[mi], bH[2], bH[3]);
                mma_f16(c1, aH[mi], bL[2], bL[3]);
                mma_f16(c1, aL[mi], bH[2], bH[3]);
            }
        }
    }
}

static __device__ __forceinline__ void gemm3(
    const __half* gAh, const __half* gAl, int ldA,
    const __half* gBh, const __half* gBl, int ldB,
    int NC, float acc[2][8][4])
{
    const uint32_t sb = smem_u32(dsm);
    stage4(gAh, gAl, ldA, gBh, gBl, ldB, sb);
    asm volatile("cp.async.commit_group;" ::: "memory");
    if (NC > 1) {
        stage4(gAh + 32, gAl + 32, ldA, gBh + 32, gBl + 32, ldB, sb + BUF_STRIDE);
        asm volatile("cp.async.commit_group;" ::: "memory");
    }
    int buf = 0;
    for (int c = 0; c < NC; ++c) {
        if (c + 1 < NC) { asm volatile("cp.async.wait_group 1;" ::: "memory"); }
        else            { asm volatile("cp.async.wait_group 0;" ::: "memory"); }
        __syncthreads();
        if (c + 2 < NC) {
            int nb = buf + 2; if (nb >= 3) nb -= 3;
            uint32_t nbo = sb + (uint32_t)nb * BUF_STRIDE;
            stage4(gAh + (size_t)(c + 2) * 32, gAl + (size_t)(c + 2) * 32, ldA,
                   gBh + (size_t)(c + 2) * 32, gBl + (size_t)(c + 2) * 32, ldB, nbo);
            asm volatile("cp.async.commit_group;" ::: "memory");
        }
        compute_chunk3(sb + (uint32_t)buf * BUF_STRIDE, acc);
        if (++buf == 3) buf = 0;
    }
    __syncthreads();
}

// ---------------------------------------------------------------------------
// 2-term GEMM core (scores/av): C = Ah*Bh + Ah*Bl (A-lo dropped).
// ---------------------------------------------------------------------------

static __device__ __forceinline__ void stage3(
    const __half* gAh, int ldA,
    const __half* gBh, const __half* gBl, int ldB, uint32_t sbuf)
{
    const int t = threadIdx.x;
    #pragma unroll
    for (int i = 0; i < 2; ++i) {
        int v   = t + i * 256;
        int row = v >> 2;
        int s   = v & 3;
        uint32_t off = SWP(row, s);
        const __half* pah = gAh + (size_t)row * ldA + s * 8;
        const __half* pbh = gBh + (size_t)row * ldB + s * 8;
        const __half* pbl = gBl + (size_t)row * ldB + s * 8;
        asm volatile("cp.async.cg.shared.global [%0], [%1], 16;" :: "r"(sbuf + off),           "l"(pah) : "memory");
        asm volatile("cp.async.cg.shared.global [%0], [%1], 16;" :: "r"(sbuf + OFF2_BH + off), "l"(pbh) : "memory");
        asm volatile("cp.async.cg.shared.global [%0], [%1], 16;" :: "r"(sbuf + OFF2_BL + off), "l"(pbl) : "memory");
    }
}

static __device__ __forceinline__ void compute_chunk2(uint32_t sbuf, float acc[2][8][4])
{
    const int lane = threadIdx.x & 31;
    const int w    = threadIdx.x >> 5;
    const int wm   = w & 3;
    const int wn   = w >> 2;
    const int r    = lane & 7;
    const int mid  = lane >> 3;

    #pragma unroll
    for (int ki = 0; ki < 2; ++ki) {
        uint32_t aH[2][4];
        #pragma unroll
        for (int mi = 0; mi < 2; ++mi) {
            int row = wm * 32 + mi * 16 + (mid & 1) * 8 + r;
            int s   = ki * 2 + (mid >> 1);
            LDSM4(aH[mi], sbuf + SWP(row, s));
        }
        #pragma unroll
        for (int pj = 0; pj < 4; ++pj) {
            uint32_t bH[4], bL[4];
            int row = wn * 64 + (pj * 2 + (mid >> 1)) * 8 + r;
            int s   = ki * 2 + (mid & 1);
            uint32_t off = SWP(row, s);
            LDSM4(bH, sbuf + OFF2_BH + off);
            LDSM4(bL, sbuf + OFF2_BL + off);
            #pragma unroll
            for (int mi = 0; mi < 2; ++mi) {
                float* c0 = acc[mi][pj * 2 + 0];
                float* c1 = acc[mi][pj * 2 + 1];
                mma_f16(c0, aH[mi], bH[0], bH[1]);
                mma_f16(c0, aH[mi], bL[0], bL[1]);
                mma_f16(c1, aH[mi], bH[2], bH[3]);
                mma_f16(c1, aH[mi], bL[2], bL[3]);
            }
        }
    }
}

static __device__ __forceinline__ void gemm2(
    const __half* gAh, int ldA,
    const __half* gBh, const __half* gBl, int ldB,
    int NC, float acc[2][8][4])
{
    const uint32_t sb = smem_u32(dsm);
    stage3(gAh, ldA, gBh, gBl, ldB, sb);
    asm volatile("cp.async.commit_group;" ::: "memory");
    if (NC > 1) {
        stage3(gAh + 32, ldA, gBh + 32, gBl + 32, ldB, sb + BUF2_STRIDE);
        asm volatile("cp.async.commit_group;" ::: "memory");
    }
    int buf = 0;
    for (int c = 0; c < NC; ++c) {
        if (c + 1 < NC) { asm volatile("cp.async.wait_group 1;" ::: "memory"); }
        else            { asm volatile("cp.async.wait_group 0;" ::: "memory"); }
        __syncthreads();
        if (c + 2 < NC) {
            int nb = buf + 2; if (nb >= 3) nb -= 3;
            uint32_t nbo = sb + (uint32_t)nb * BUF2_STRIDE;
            stage3(gAh + (size_t)(c + 2) * 32, ldA,
                   gBh + (size_t)(c + 2) * 32, gBl + (size_t)(c + 2) * 32, ldB, nbo);
            asm volatile("cp.async.commit_group;" ::: "memory");
        }
        compute_chunk2(sb + (uint32_t)buf * BUF2_STRIDE, acc);
        if (++buf == 3) buf = 0;
    }
    __syncthreads();
}

// Epilogue coords: row = wm*32 + mi*16 + (lane>>2) (+8); col = wn*64 + j*8 + (lane&3)*2 (+1)
//   acc[mi][j] = {c(row,col), c(row,col+1), c(row+8,col), c(row+8,col+1)}

// ---------------------------------------------------------------------------
// Kernel 0: elementwise fp32 -> fp16 hi/lo split (float4 vectorized)
// ---------------------------------------------------------------------------
__global__ void __launch_bounds__(256) split_kernel(
    const float* __restrict__ src, __half* __restrict__ hi, __half* __restrict__ lo, int n4)
{
    int i = blockIdx.x * blockDim.x + threadIdx.x;
    if (i >= n4) return;
    float4 v = ((const float4*)src)[i];
    __half hx = __float2half_rn(v.x), hy = __float2half_rn(v.y);
    __half hz = __float2half_rn(v.z), hw = __float2half_rn(v.w);
    __half lx = __float2half_rn(v.x - __half2float(hx));
    __half ly = __float2half_rn(v.y - __half2float(hy));
    __half lz = __float2half_rn(v.z - __half2float(hz));
    __half lw = __float2half_rn(v.w - __half2float(hw));
    ((__half2*)hi)[2 * i]     = __halves2half2(hx, hy);
    ((__half2*)hi)[2 * i + 1] = __halves2half2(hz, hw);
    ((__half2*)lo)[2 * i]     = __halves2half2(lx, ly);
    ((__half2*)lo)[2 * i + 1] = __halves2half2(lz, lw);
}

// ---------------------------------------------------------------------------
// Kernel 1: QKV projection (3-term). z==0 -> Qh only; z==1 -> Kh,Kl;
// z==2 -> transposed Vth,Vtl via smem transpose.
// ---------------------------------------------------------------------------
__global__ void __launch_bounds__(256, 2) qkv_kernel(
    const float* __restrict__ bq, const float* __restrict__ bk, const float* __restrict__ bv)
{
    const int z = blockIdx.z;
    const float* bias = (z == 0) ? bq : (z == 1) ? bk : bv;
    const int m0 = blockIdx.y * 128;
    const int n0 = blockIdx.x * 128;

    float acc[2][8][4] = {};
    gemm3(g_Xh + (size_t)m0 * FF, g_Xl + (size_t)m0 * FF, FF,
          g_Wh + (size_t)z * FF * FF + (size_t)n0 * FF,
          g_Wl + (size_t)z * FF * FF + (size_t)n0 * FF, FF, FF / 32, acc);

    const int lane = threadIdx.x & 31;
    const int w    = threadIdx.x >> 5;
    const int wm = w & 3, wn = w >> 2;
    const int g = lane >> 2, tq = lane & 3;

    if (z == 0) {
        // Q: hi only (2-term scores never reads Q-lo)
        #pragma unroll
        for (int mi = 0; mi < 2; ++mi) {
            int row = m0 + wm * 32 + mi * 16 + g;
            #pragma unroll
            for (int j = 0; j < 8; ++j) {
                int col = n0 + wn * 64 + j * 8 + tq * 2;
                float2 b2 = *(const float2*)&bias[col];
                float v0 = acc[mi][j][0] + b2.x, v1 = acc[mi][j][1] + b2.y;
                float v2 = acc[mi][j][2] + b2.x, v3 = acc[mi][j][3] + b2.y;
                *(__half2*)&g_Qh[(size_t)row * FF + col] =
                    __halves2half2(__float2half_rn(v0), __float2half_rn(v1));
                *(__half2*)&g_Qh[(size_t)(row + 8) * FF + col] =
                    __halves2half2(__float2half_rn(v2), __float2half_rn(v3));
            }
        }
    } else if (z == 1) {
        #pragma unroll
        for (int mi = 0; mi < 2; ++mi) {
            int row = m0 + wm * 32 + mi * 16 + g;
            #pragma unroll
            for (int j = 0; j < 8; ++j) {
                int col = n0 + wn * 64 + j * 8 + tq * 2;
                float2 b2 = *(const float2*)&bias[col];
                split_store_h2(g_Kh, g_Kl, (size_t)row * FF + col,
                               acc[mi][j][0] + b2.x, acc[mi][j][1] + b2.y);
                split_store_h2(g_Kh, g_Kl, (size_t)(row + 8) * FF + col,
                               acc[mi][j][2] + b2.x, acc[mi][j][3] + b2.y);
            }
        }
    } else {
        float* st = (float*)dsm;   // [128][132] fp32 transpose staging
        #pragma unroll
        for (int mi = 0; mi < 2; ++mi) {
            int row = wm * 32 + mi * 16 + g;
            #pragma unroll
            for (int j = 0; j < 8; ++j) {
                int col = wn * 64 + j * 8 + tq * 2;
                float2 b2 = *(const float2*)&bias[n0 + col];
                st[(size_t)row * 132 + col]           = acc[mi][j][0] + b2.x;
                st[(size_t)row * 132 + col + 1]       = acc[mi][j][1] + b2.y;
                st[(size_t)(row + 8) * 132 + col]     = acc[mi][j][2] + b2.x;
                st[(size_t)(row + 8) * 132 + col + 1] = acc[mi][j][3] + b2.y;
            }
        }
        __syncthreads();
        const int f  = threadIdx.x & 127;
        const int sh = threadIdx.x >> 7;
        const int b  = m0 >> 11;           // tile never straddles a batch
        const int s0 = m0 & (SS - 1);
        size_t base = ((size_t)b * FF + (n0 + f)) * SS + s0 + sh * 64;
        #pragma unroll
        for (int jj = 0; jj < 32; ++jj) {
            float v0 = st[(size_t)(sh * 64 + 2 * jj + 0) * 132 + f];
            float v1 = st[(size_t)(sh * 64 + 2 * jj + 1) * 132 + f];
            split_store_h2(g_Vth, g_Vtl, base + 2 * jj, v0, v1);
        }
    }
}

// ---------------------------------------------------------------------------
// Kernel 2: scores = scale * Q @ K^T (2-term), causal tile skip, masks fused.
// ---------------------------------------------------------------------------
__global__ void __launch_bounds__(256, 2) scores_kernel(const int* __restrict__ pad_mask)
{
    const int kt = blockIdx.x, qt = blockIdx.y, b = blockIdx.z;
    if (kt > qt) return;
    const int m0 = qt * 128, n0 = kt * 128;

    float acc[2][8][4] = {};
    gemm2(g_Qh + ((size_t)b * SS + m0) * FF, FF,
          g_Kh + ((size_t)b * SS + n0) * FF, g_Kl + ((size_t)b * SS + n0) * FF, FF,
          FF / 32, acc);

    const int lane = threadIdx.x & 31;
    const int w    = threadIdx.x >> 5;
    const int wm = w & 3, wn = w >> 2;
    const int g = lane >> 2, tq = lane & 3;

    float* P = g_S + (size_t)b * SS * SS;
    const int* pm = pad_mask + (size_t)b * SS;
    const float scale = 0.03125f;  // 1/sqrt(1024)

    #pragma unroll
    for (int mi = 0; mi < 2; ++mi) {
        int q0 = m0 + wm * 32 + mi * 16 + g;
        #pragma unroll
        for (int j = 0; j < 8; ++j) {
            int col = n0 + wn * 64 + j * 8 + tq * 2;
            int2 p2 = *(const int2*)&pm[col];
            float2 o0, o1;
            o0.x = (p2.x == 0 || col     > q0) ? NEGV : acc[mi][j][0] * scale;
            o0.y = (p2.y == 0 || col + 1 > q0) ? NEGV : acc[mi][j][1] * scale;
            int q1 = q0 + 8;
            o1.x = (p2.x == 0 || col     > q1) ? NEGV : acc[mi][j][2] * scale;
            o1.y = (p2.y == 0 || col + 1 > q1) ? NEGV : acc[mi][j][3] * scale;
            *(float2*)&P[(size_t)q0 * SS + col] = o0;
            *(float2*)&P[(size_t)q1 * SS + col] = o1;
        }
    }
}

// ---------------------------------------------------------------------------
// Kernel 3: warp-per-row softmax, no __syncthreads. Writes P-hi only
// (2-term AV never reads P-lo). Masked entries of g_S are NEGV -> exact zeros.
// ---------------------------------------------------------------------------
__global__ void __launch_bounds__(256) softmax_kernel()
{
    const int warp = threadIdx.x >> 5;
    const int lane = threadIdx.x & 31;
    const int q = blockIdx.x * 8 + warp;
    const int b = blockIdx.y;
    const size_t ro = (size_t)b * SS * SS + (size_t)q * SS;
    const float4* row4 = (const float4*)(g_S + ro);
    const int nch = (q >> 7) + 1;          // 128-element chunks in causal span

    float4 v[16];
    float m = -3.4e38f;
    #pragma unroll
    for (int i = 0; i < 16; ++i) {
        if (i < nch) {
            v[i] = row4[i * 32 + lane];
            m = fmaxf(m, fmaxf(fmaxf(v[i].x, v[i].y), fmaxf(v[i].z, v[i].w)));
        }
    }
    #pragma unroll
    for (int o = 16; o > 0; o >>= 1) m = fmaxf(m, __shfl_xor_sync(0xffffffffu, m, o));

    float s = 0.f;
    #pragma unroll
    for (int i = 0; i < 16; ++i) {
        if (i < nch) {
            v[i].x = __expf(v[i].x - m); v[i].y = __expf(v[i].y - m);
            v[i].z = __expf(v[i].z - m); v[i].w = __expf(v[i].w - m);
            s += (v[i].x + v[i].y) + (v[i].z + v[i].w);
        }
    }
    #pragma unroll
    for (int o = 16; o > 0; o >>= 1) s += __shfl_xor_sync(0xffffffffu, s, o);
    const float inv = 1.0f / s;

    #pragma unroll
    for (int i = 0; i < 16; ++i) {
        if (i < nch) {
            size_t off = ro + (size_t)i * 128 + lane * 4;
            __half h0 = __float2half_rn(v[i].x * inv);
            __half h1 = __float2half_rn(v[i].y * inv);
            __half h2 = __float2half_rn(v[i].z * inv);
            __half h3 = __float2half_rn(v[i].w * inv);
            *(__half2*)&g_Ph[off]     = __halves2half2(h0, h1);
            *(__half2*)&g_Ph[off + 2] = __halves2half2(h2, h3);
        }
    }
}

// ---------------------------------------------------------------------------
// Kernel 4: out = P @ Vt^T (2-term), K truncated at the causal 128-boundary.
// Heavy (high-qt) tiles launch FIRST (LPT scheduling) via qt remap.
// ---------------------------------------------------------------------------
__global__ void __launch_bounds__(256, 2) av_kernel(float* __restrict__ out)
{
    const int n0 = blockIdx.x * 128, b = blockIdx.z;
    const int qt = (SS / 128 - 1) - blockIdx.y;   // descending work order
    const int m0 = qt * 128;

    float acc[2][8][4] = {};
    gemm2(g_Ph  + ((size_t)b * SS + m0) * SS, SS,
          g_Vth + ((size_t)b * FF + n0) * SS, g_Vtl + ((size_t)b * FF + n0) * SS, SS,
          (qt + 1) * 4, acc);

    const int lane = threadIdx.x & 31;
    const int w    = threadIdx.x >> 5;
    const int wm = w & 3, wn = w >> 2;
    const int g = lane >> 2, tq = lane & 3;

    float* C = out + (size_t)b * SS * FF;
    #pragma unroll
    for (int mi = 0; mi < 2; ++mi) {
        int row = m0 + wm * 32 + mi * 16 + g;
        #pragma unroll
        for (int j = 0; j < 8; ++j) {
            int col = n0 + wn * 64 + j * 8 + tq * 2;
            float2 o0 = { acc[mi][j][0], acc[mi][j][1] };
            float2 o1 = { acc[mi][j][2], acc[mi][j][3] };
            *(float2*)&C[(size_t)row * FF + col]       = o0;
            *(float2*)&C[(size_t)(row + 8) * FF + col] = o1;
        }
    }
}

extern "C" void kernel_launch(void* const* d_in, const int* in_sizes, int n_in,
                              void* d_out, int out_size)
{
    const float* x        = (const float*)d_in[0];
    // d_in[1] = attn_mask (exact causal tril, handled analytically)
    const int*   pad_mask = (const int*)d_in[2];
    const float* Wq = (const float*)d_in[3];
    const float* bq = (const float*)d_in[4];
    const float* Wk = (const float*)d_in[5];
    const float* bk = (const float*)d_in[6];
    const float* Wv = (const float*)d_in[7];
    const float* bv = (const float*)d_in[8];
    float* out = (float*)d_out;

    __half *xh, *xl, *wh, *wl;
    cudaGetSymbolAddress((void**)&xh, g_Xh);
    cudaGetSymbolAddress((void**)&xl, g_Xl);
    cudaGetSymbolAddress((void**)&wh, g_Wh);
    cudaGetSymbolAddress((void**)&wl, g_Wl);

    cudaFuncSetAttribute(qkv_kernel,    cudaFuncAttributeMaxDynamicSharedMemorySize, SMEM_BYTES);
    cudaFuncSetAttribute(scores_kernel, cudaFuncAttributeMaxDynamicSharedMemorySize, SMEM_BYTES2);
    cudaFuncSetAttribute(av_kernel,     cudaFuncAttributeMaxDynamicSharedMemorySize, SMEM_BYTES2);

    dim3 blk(256);
    const int nx4 = BB * SS * FF / 4;
    const int nw4 = FF * FF / 4;
    split_kernel<<<(nx4 + 255) / 256, blk>>>(x,  xh, xl, nx4);
    split_kernel<<<(nw4 + 255) / 256, blk>>>(Wq, wh,               wl,               nw4);
    split_kernel<<<(nw4 + 255) / 256, blk>>>(Wk, wh + FF * FF,     wl + FF * FF,     nw4);
    split_kernel<<<(nw4 + 255) / 256, blk>>>(Wv, wh + 2 * FF * FF, wl + 2 * FF * FF, nw4);

    qkv_kernel   <<<dim3(FF / 128, (BB * SS) / 128, 3), blk, SMEM_BYTES>>>(bq, bk, bv);
    scores_kernel<<<dim3(SS / 128, SS / 128, BB),        blk, SMEM_BYTES2>>>(pad_mask);
    softmax_kernel<<<dim3(SS / 8, BB),                   blk>>>();
    av_kernel    <<<dim3(FF / 128, SS / 128, BB),        blk, SMEM_BYTES2>>>(out);
}

// round 15
// speedup vs baseline: 1.3472x; 1.3472x over previous
#include <cuda_runtime.h>
#include <cuda_fp16.h>
#include <cstdint>

#define BB 8
#define SS 2048
#define FF 1024
#define NEGV -1000000000.0f

// Persistent hi/lo split operands, fp16 (allocation-free rule: __device__ globals)
__device__ __half g_Xh [BB * SS * FF];
__device__ __half g_Xl [BB * SS * FF];
__device__ __half g_Wh [3 * FF * FF];
__device__ __half g_Wl [3 * FF * FF];
__device__ __half g_Qh [BB * SS * FF];
__device__ __half g_Ql [BB * SS * FF];
__device__ __half g_Kh [BB * SS * FF];
__device__ __half g_Kl [BB * SS * FF];
__device__ __half g_Vth[BB * FF * SS];   // V transposed [b][f][s]
__device__ __half g_Vtl[BB * FF * SS];
__device__ float  g_S  [BB * SS * SS];   // raw masked scores (fp32)
__device__ __half g_Ph [BB * SS * SS];   // probs hi/lo
__device__ __half g_Pl [BB * SS * SS];

// Dynamic smem: TRIPLE-buffered 4-tile chunks, K=32 fp16 per chunk.
//   stage = [Ah 8K][Al 8K][Bh 8K][Bl 8K] = 32K; three stages = 96K.
// qkv V-transpose epilogue reuses [0, 128*132*4)=67584 after pipeline drains.
extern __shared__ __align__(1024) char dsm[];
#define BUF_STRIDE 32768u
#define OFF_AL  8192u
#define OFF_BH 16384u
#define OFF_BL 24576u
#define SMEM_BYTES 98304   // 3 * 32K

#define SW128(o) ((o) ^ (((o) >> 3) & 0x70))
// Packed tile: two 64B tile-rows (32 fp16 each) per 128B smem row, SW128 swizzled.
// row in [0,128), s = 16B segment (8 fp16) in [0,4)
#define SWP(row, s) SW128((((row) >> 1) * 128) + (((((row) & 1) * 4) + (s)) * 16))

static __device__ __forceinline__ uint32_t smem_u32(const void* p) {
    uint32_t a;
    asm("{ .reg .u64 t; cvta.to.shared.u64 t, %1; cvt.u32.u64 %0, t; }" : "=r"(a) : "l"(p));
    return a;
}
// Paired split: writes half2 at even element index
static __device__ __forceinline__ void split_store_h2(
    __half* __restrict__ hi, __half* __restrict__ lo, size_t idx, float v0, float v1)
{
    __half h0 = __float2half_rn(v0);
    __half h1 = __float2half_rn(v1);
    __half l0 = __float2half_rn(v0 - __half2float(h0));
    __half l1 = __float2half_rn(v1 - __half2float(h1));
    *(__half2*)&hi[idx] = __halves2half2(h0, h1);
    *(__half2*)&lo[idx] = __halves2half2(l0, l1);
}

// ---------------------------------------------------------------------------
// 3xFP16 GEMM core on pre-split operands. 128x128 tile, K chunks of 32.
// 256 threads = 8 warps, 4(m) x 2(n); warp tile 32x64.
// m16n8k16 f16 MMA with fp32 accum: C = Ah*Bh + Ah*Bl + Al*Bh.
// NT form: C[m,n] = sum_k A[m,k] * B[n,k]  (both K-contiguous rows).
// 3-stage cp.async pipeline, ONE __syncthreads per chunk.
// ---------------------------------------------------------------------------

static __device__ __forceinline__ void stage4(
    const __half* gAh, const __half* gAl, int ldA,
    const __half* gBh, const __half* gBl, int ldB, uint32_t sbuf)
{
    const int t = threadIdx.x;
    #pragma unroll
    for (int i = 0; i < 2; ++i) {
        int v   = t + i * 256;          // 512 16B segments per tile
        int row = v >> 2;               // 0..127
        int s   = v & 3;                // 16B segment (8 fp16) within 64B row
        uint32_t off = SWP(row, s);
        const __half* pah = gAh + (size_t)row * ldA + s * 8;
        const __half* pal = gAl + (size_t)row * ldA + s * 8;
        const __half* pbh = gBh + (size_t)row * ldB + s * 8;
        const __half* pbl = gBl + (size_t)row * ldB + s * 8;
        asm volatile("cp.async.cg.shared.global [%0], [%1], 16;" :: "r"(sbuf + off),          "l"(pah) : "memory");
        asm volatile("cp.async.cg.shared.global [%0], [%1], 16;" :: "r"(sbuf + OFF_AL + off), "l"(pal) : "memory");
        asm volatile("cp.async.cg.shared.global [%0], [%1], 16;" :: "r"(sbuf + OFF_BH + off), "l"(pbh) : "memory");
        asm volatile("cp.async.cg.shared.global [%0], [%1], 16;" :: "r"(sbuf + OFF_BL + off), "l"(pbl) : "memory");
    }
}

// NOTE: non-volatile — pure register math; lets ptxas interleave with LDSM.
static __device__ __forceinline__ void mma_f16(float* c, const uint32_t* a,
                                               uint32_t b0, uint32_t b1)
{
    asm("mma.sync.aligned.m16n8k16.row.col.f32.f16.f16.f32 "
        "{%0,%1,%2,%3}, {%4,%5,%6,%7}, {%8,%9}, {%0,%1,%2,%3};"
        : "+f"(c[0]), "+f"(c[1]), "+f"(c[2]), "+f"(c[3])
        : "r"(a[0]), "r"(a[1]), "r"(a[2]), "r"(a[3]), "r"(b0), "r"(b1));
}

#define LDSM4(dst, addr) \
    asm volatile("ldmatrix.sync.aligned.m8n8.x4.shared.b16 {%0,%1,%2,%3}, [%4];" \
        : "=r"((dst)[0]), "=r"((dst)[1]), "=r"((dst)[2]), "=r"((dst)[3]) : "r"(addr))

static __device__ __forceinline__ void compute_chunk(uint32_t sbuf, float acc[2][8][4])
{
    const int lane = threadIdx.x & 31;
    const int w    = threadIdx.x >> 5;
    const int wm   = w & 3;
    const int wn   = w >> 2;
    const int r    = lane & 7;
    const int mid  = lane >> 3;

    #pragma unroll
    for (int ki = 0; ki < 2; ++ki) {
        uint32_t aH[2][4], aL[2][4];
        #pragma unroll
        for (int mi = 0; mi < 2; ++mi) {
            int row = wm * 32 + mi * 16 + (mid & 1) * 8 + r;
            int s   = ki * 2 + (mid >> 1);
            uint32_t off = SWP(row, s);
            LDSM4(aH[mi], sbuf + off);
            LDSM4(aL[mi], sbuf + OFF_AL + off);
        }
        #pragma unroll
        for (int pj = 0; pj < 4; ++pj) {
            uint32_t bH[4], bL[4];
            int row = wn * 64 + (pj * 2 + (mid >> 1)) * 8 + r;
            int s   = ki * 2 + (mid & 1);
            uint32_t off = SWP(row, s);
            LDSM4(bH, sbuf + OFF_BH + off);
            LDSM4(bL, sbuf + OFF_BL + off);
            #pragma unroll
            for (int mi = 0; mi < 2; ++mi) {
                float* c0 = acc[mi][pj * 2 + 0];
                float* c1 = acc[mi][pj * 2 + 1];
                mma_f16(c0, aH[mi], bH[0], bH[1]);
                mma_f16(c0, aH[mi], bL[0], bL[1]);
                mma_f16(c0, aL[mi], bH[0], bH[1]);
                mma_f16(c1, aH[mi], bH[2], bH[3]);
                mma_f16(c1, aH[mi], bL[2], bL[3]);
                mma_f16(c1, aL[mi], bH[2], bH[3]);
            }
        }
    }
}

// NC counts K chunks of 32. 3-stage pipeline, single barrier per chunk.
static __device__ __forceinline__ void gemm(
    const __half* gAh, const __half* gAl, int ldA,
    const __half* gBh, const __half* gBl, int ldB,
    int NC, float acc[2][8][4])
{
    const uint32_t sb = smem_u32(dsm);
    stage4(gAh, gAl, ldA, gBh, gBl, ldB, sb);
    asm volatile("cp.async.commit_group;" ::: "memory");
    if (NC > 1) {
        stage4(gAh + 32, gAl + 32, ldA, gBh + 32, gBl + 32, ldB, sb + BUF_STRIDE);
        asm volatile("cp.async.commit_group;" ::: "memory");
    }
    int buf = 0;                 // = c % 3
    for (int c = 0; c < NC; ++c) {
        if (c + 1 < NC) { asm volatile("cp.async.wait_group 1;" ::: "memory"); }
        else            { asm volatile("cp.async.wait_group 0;" ::: "memory"); }
        __syncthreads();
        if (c + 2 < NC) {
            int nb = buf + 2; if (nb >= 3) nb -= 3;   // (c+2) % 3
            uint32_t nbo = sb + (uint32_t)nb * BUF_STRIDE;
            stage4(gAh + (size_t)(c + 2) * 32, gAl + (size_t)(c + 2) * 32, ldA,
                   gBh + (size_t)(c + 2) * 32, gBl + (size_t)(c + 2) * 32, ldB, nbo);
            asm volatile("cp.async.commit_group;" ::: "memory");
        }
        compute_chunk(sb + (uint32_t)buf * BUF_STRIDE, acc);
        if (++buf == 3) buf = 0;
    }
    __syncthreads();   // epilogues may reuse dsm
}

// Epilogue coords: row = wm*32 + mi*16 + (lane>>2) (+8); col = wn*64 + j*8 + (lane&3)*2 (+1)
//   acc[mi][j] = {c(row,col), c(row,col+1), c(row+8,col), c(row+8,col+1)}

// ---------------------------------------------------------------------------
// Kernel 0: fused fp32 -> fp16 hi/lo split for x, Wq, Wk, Wv in ONE launch.
// Blocks [0, nx4/256) cover x; the rest cover the three W matrices packed
// contiguously into g_Wh/g_Wl.
// ---------------------------------------------------------------------------
__global__ void __launch_bounds__(256) split_all_kernel(
    const float* __restrict__ x,
    const float* __restrict__ Wq, const float* __restrict__ Wk, const float* __restrict__ Wv,
    __half* __restrict__ xh, __half* __restrict__ xl,
    __half* __restrict__ wh, __half* __restrict__ wl)
{
    const int nx4 = BB * SS * FF / 4;
    const int nw4 = FF * FF / 4;
    int i = blockIdx.x * blockDim.x + threadIdx.x;

    const float* src;
    __half *hi, *lo;
    int idx;
    if (i < nx4) {
        src = x; hi = xh; lo = xl; idx = i;
    } else {
        int j = i - nx4;                 // 0 .. 3*nw4-1
        int wsel = j / nw4;              // 0,1,2
        idx = j - wsel * nw4;
        src = (wsel == 0) ? Wq : (wsel == 1) ? Wk : Wv;
        hi = wh + (size_t)wsel * FF * FF;
        lo = wl + (size_t)wsel * FF * FF;
    }

    float4 v = ((const float4*)src)[idx];
    __half hx = __float2half_rn(v.x), hy = __float2half_rn(v.y);
    __half hz = __float2half_rn(v.z), hw = __float2half_rn(v.w);
    __half lx = __float2half_rn(v.x - __half2float(hx));
    __half ly = __float2half_rn(v.y - __half2float(hy));
    __half lz = __float2half_rn(v.z - __half2float(hz));
    __half lw = __float2half_rn(v.w - __half2float(hw));
    ((__half2*)hi)[2 * idx]     = __halves2half2(hx, hy);
    ((__half2*)hi)[2 * idx + 1] = __halves2half2(hz, hw);
    ((__half2*)lo)[2 * idx]     = __halves2half2(lx, ly);
    ((__half2*)lo)[2 * idx + 1] = __halves2half2(lz, lw);
}

// ---------------------------------------------------------------------------
// Kernel 1: QKV projection; outputs split (Qh,Ql)/(Kh,Kl)/(Vth,Vtl).
// ---------------------------------------------------------------------------
__global__ void __launch_bounds__(256, 2) qkv_kernel(
    const float* __restrict__ bq, const float* __restrict__ bk, const float* __restrict__ bv)
{
    const int z = blockIdx.z;
    const float* bias = (z == 0) ? bq : (z == 1) ? bk : bv;
    const int m0 = blockIdx.y * 128;
    const int n0 = blockIdx.x * 128;

    float acc[2][8][4] = {};
    gemm(g_Xh + (size_t)m0 * FF, g_Xl + (size_t)m0 * FF, FF,
         g_Wh + (size_t)z * FF * FF + (size_t)n0 * FF,
         g_Wl + (size_t)z * FF * FF + (size_t)n0 * FF, FF, FF / 32, acc);

    const int lane = threadIdx.x & 31;
    const int w    = threadIdx.x >> 5;
    const int wm = w & 3, wn = w >> 2;
    const int g = lane >> 2, tq = lane & 3;

    if (z < 2) {
        __half* H = (z == 0 ? g_Qh : g_Kh);
        __half* L = (z == 0 ? g_Ql : g_Kl);
        #pragma unroll
        for (int mi = 0; mi < 2; ++mi) {
            int row = m0 + wm * 32 + mi * 16 + g;
            #pragma unroll
            for (int j = 0; j < 8; ++j) {
                int col = n0 + wn * 64 + j * 8 + tq * 2;
                float2 b2 = *(const float2*)&bias[col];
                split_store_h2(H, L, (size_t)row * FF + col,
                               acc[mi][j][0] + b2.x, acc[mi][j][1] + b2.y);
                split_store_h2(H, L, (size_t)(row + 8) * FF + col,
                               acc[mi][j][2] + b2.x, acc[mi][j][3] + b2.y);
            }
        }
    } else {
        float* st = (float*)dsm;   // [128][132] fp32 transpose staging
        #pragma unroll
        for (int mi = 0; mi < 2; ++mi) {
            int row = wm * 32 + mi * 16 + g;
            #pragma unroll
            for (int j = 0; j < 8; ++j) {
                int col = wn * 64 + j * 8 + tq * 2;
                float2 b2 = *(const float2*)&bias[n0 + col];
                st[(size_t)row * 132 + col]           = acc[mi][j][0] + b2.x;
                st[(size_t)row * 132 + col + 1]       = acc[mi][j][1] + b2.y;
                st[(size_t)(row + 8) * 132 + col]     = acc[mi][j][2] + b2.x;
                st[(size_t)(row + 8) * 132 + col + 1] = acc[mi][j][3] + b2.y;
            }
        }
        __syncthreads();
        const int f  = threadIdx.x & 127;
        const int sh = threadIdx.x >> 7;
        const int b  = m0 >> 11;           // tile never straddles a batch
        const int s0 = m0 & (SS - 1);
        size_t base = ((size_t)b * FF + (n0 + f)) * SS + s0 + sh * 64;
        #pragma unroll
        for (int jj = 0; jj < 32; ++jj) {
            float v0 = st[(size_t)(sh * 64 + 2 * jj + 0) * 132 + f];
            float v1 = st[(size_t)(sh * 64 + 2 * jj + 1) * 132 + f];
            split_store_h2(g_Vth, g_Vtl, base + 2 * jj, v0, v1);
        }
    }
}

// ---------------------------------------------------------------------------
// Kernel 2: scores = scale * Q @ K^T, causal tile skip, masks fused -> g_S.
// ---------------------------------------------------------------------------
__global__ void __launch_bounds__(256, 2) scores_kernel(const int* __restrict__ pad_mask)
{
    const int kt = blockIdx.x, qt = blockIdx.y, b = blockIdx.z;
    if (kt > qt) return;
    const int m0 = qt * 128, n0 = kt * 128;

    float acc[2][8][4] = {};
    gemm(g_Qh + ((size_t)b * SS + m0) * FF, g_Ql + ((size_t)b * SS + m0) * FF, FF,
         g_Kh + ((size_t)b * SS + n0) * FF, g_Kl + ((size_t)b * SS + n0) * FF, FF,
         FF / 32, acc);

    const int lane = threadIdx.x & 31;
    const int w    = threadIdx.x >> 5;
    const int wm = w & 3, wn = w >> 2;
    const int g = lane >> 2, tq = lane & 3;

    float* P = g_S + (size_t)b * SS * SS;
    const int* pm = pad_mask + (size_t)b * SS;
    const float scale = 0.03125f;  // 1/sqrt(1024)

    #pragma unroll
    for (int mi = 0; mi < 2; ++mi) {
        int q0 = m0 + wm * 32 + mi * 16 + g;
        #pragma unroll
        for (int j = 0; j < 8; ++j) {
            int col = n0 + wn * 64 + j * 8 + tq * 2;
            int2 p2 = *(const int2*)&pm[col];
            float2 o0, o1;
            o0.x = (p2.x == 0 || col     > q0) ? NEGV : acc[mi][j][0] * scale;
            o0.y = (p2.y == 0 || col + 1 > q0) ? NEGV : acc[mi][j][1] * scale;
            int q1 = q0 + 8;
            o1.x = (p2.x == 0 || col     > q1) ? NEGV : acc[mi][j][2] * scale;
            o1.y = (p2.y == 0 || col + 1 > q1) ? NEGV : acc[mi][j][3] * scale;
            *(float2*)&P[(size_t)q0 * SS + col] = o0;
            *(float2*)&P[(size_t)q1 * SS + col] = o1;
        }
    }
}

// ---------------------------------------------------------------------------
// Kernel 3: warp-per-row softmax, no __syncthreads.
// Within [0, kEnd) the masked entries of g_S are already NEGV, so softmax over
// the 128-aligned span equals the true softmax and writes exact zeros at
// masked positions (what AV needs). 8 warps/block = 8 rows.
// ---------------------------------------------------------------------------
__global__ void __launch_bounds__(256) softmax_kernel()
{
    const int warp = threadIdx.x >> 5;
    const int lane = threadIdx.x & 31;
    const int q = blockIdx.x * 8 + warp;
    const int b = blockIdx.y;
    const size_t ro = (size_t)b * SS * SS + (size_t)q * SS;
    const float4* row4 = (const float4*)(g_S + ro);
    const int nch = (q >> 7) + 1;          // 128-element chunks in causal span

    float4 v[16];
    float m = -3.4e38f;
    #pragma unroll
    for (int i = 0; i < 16; ++i) {
        if (i < nch) {
            v[i] = row4[i * 32 + lane];
            m = fmaxf(m, fmaxf(fmaxf(v[i].x, v[i].y), fmaxf(v[i].z, v[i].w)));
        }
    }
    #pragma unroll
    for (int o = 16; o > 0; o >>= 1) m = fmaxf(m, __shfl_xor_sync(0xffffffffu, m, o));

    float s = 0.f;
    #pragma unroll
    for (int i = 0; i < 16; ++i) {
        if (i < nch) {
            v[i].x = __expf(v[i].x - m); v[i].y = __expf(v[i].y - m);
            v[i].z = __expf(v[i].z - m); v[i].w = __expf(v[i].w - m);
            s += (v[i].x + v[i].y) + (v[i].z + v[i].w);
        }
    }
    #pragma unroll
    for (int o = 16; o > 0; o >>= 1) s += __shfl_xor_sync(0xffffffffu, s, o);
    const float inv = 1.0f / s;

    #pragma unroll
    for (int i = 0; i < 16; ++i) {
        if (i < nch) {
            float p0 = v[i].x * inv, p1 = v[i].y * inv;
            float p2 = v[i].z * inv, p3 = v[i].w * inv;
            size_t off = ro + (size_t)i * 128 + lane * 4;
            __half h0 = __float2half_rn(p0), h1 = __float2half_rn(p1);
            __half h2 = __float2half_rn(p2), h3 = __float2half_rn(p3);
            *(__half2*)&g_Ph[off]     = __halves2half2(h0, h1);
            *(__half2*)&g_Ph[off + 2] = __halves2half2(h2, h3);
            __half l0 = __float2half_rn(p0 - __half2float(h0));
            __half l1 = __float2half_rn(p1 - __half2float(h1));
            __half l2 = __float2half_rn(p2 - __half2float(h2));
            __half l3 = __float2half_rn(p3 - __half2float(h3));
            *(__half2*)&g_Pl[off]     = __halves2half2(l0, l1);
            *(__half2*)&g_Pl[off + 2] = __halves2half2(l2, l3);
        }
    }
}

// ---------------------------------------------------------------------------
// Kernel 4: out = P @ Vt^T, K truncated at the causal 128-boundary.
// Heavy (high-qt) tiles launch FIRST (LPT scheduling) via qt remap.
// ---------------------------------------------------------------------------
__global__ void __launch_bounds__(256, 2) av_kernel(float* __restrict__ out)
{
    const int n0 = blockIdx.x * 128, b = blockIdx.z;
    const int qt = (SS / 128 - 1) - blockIdx.y;   // descending work order
    const int m0 = qt * 128;

    float acc[2][8][4] = {};
    gemm(g_Ph  + ((size_t)b * SS + m0) * SS, g_Pl  + ((size_t)b * SS + m0) * SS, SS,
         g_Vth + ((size_t)b * FF + n0) * SS, g_Vtl + ((size_t)b * FF + n0) * SS, SS,
         (qt + 1) * 4, acc);

    const int lane = threadIdx.x & 31;
    const int w    = threadIdx.x >> 5;
    const int wm = w & 3, wn = w >> 2;
    const int g = lane >> 2, tq = lane & 3;

    float* C = out + (size_t)b * SS * FF;
    #pragma unroll
    for (int mi = 0; mi < 2; ++mi) {
        int row = m0 + wm * 32 + mi * 16 + g;
        #pragma unroll
        for (int j = 0; j < 8; ++j) {
            int col = n0 + wn * 64 + j * 8 + tq * 2;
            float2 o0 = { acc[mi][j][0], acc[mi][j][1] };
            float2 o1 = { acc[mi][j][2], acc[mi][j][3] };
            *(float2*)&C[(size_t)row * FF + col]       = o0;
            *(float2*)&C[(size_t)(row + 8) * FF + col] = o1;
        }
    }
}

extern "C" void kernel_launch(void* const* d_in, const int* in_sizes, int n_in,
                              void* d_out, int out_size)
{
    const float* x        = (const float*)d_in[0];
    // d_in[1] = attn_mask (exact causal tril, handled analytically)
    const int*   pad_mask = (const int*)d_in[2];
    const float* Wq = (const float*)d_in[3];
    const float* bq = (const float*)d_in[4];
    const float* Wk = (const float*)d_in[5];
    const float* bk = (const float*)d_in[6];
    const float* Wv = (const float*)d_in[7];
    const float* bv = (const float*)d_in[8];
    float* out = (float*)d_out;

    __half *xh, *xl, *wh, *wl;
    cudaGetSymbolAddress((void**)&xh, g_Xh);
    cudaGetSymbolAddress((void**)&xl, g_Xl);
    cudaGetSymbolAddress((void**)&wh, g_Wh);
    cudaGetSymbolAddress((void**)&wl, g_Wl);

    cudaFuncSetAttribute(qkv_kernel,    cudaFuncAttributeMaxDynamicSharedMemorySize, SMEM_BYTES);
    cudaFuncSetAttribute(scores_kernel, cudaFuncAttributeMaxDynamicSharedMemorySize, SMEM_BYTES);
    cudaFuncSetAttribute(av_kernel,     cudaFuncAttributeMaxDynamicSharedMemorySize, SMEM_BYTES);

    dim3 blk(256);
    const int nx4 = BB * SS * FF / 4;
    const int nw4 = FF * FF / 4;
    split_all_kernel<<<(nx4 + 3 * nw4 + 255) / 256, blk>>>(x, Wq, Wk, Wv, xh, xl, wh, wl);

    qkv_kernel   <<<dim3(FF / 128, (BB * SS) / 128, 3), blk, SMEM_BYTES>>>(bq, bk, bv);
    scores_kernel<<<dim3(SS / 128, SS / 128, BB),        blk, SMEM_BYTES>>>(pad_mask);
    softmax_kernel<<<dim3(SS / 8, BB),                   blk>>>();
    av_kernel    <<<dim3(FF / 128, SS / 128, BB),        blk, SMEM_BYTES>>>(out);
}